// round 1
// baseline (speedup 1.0000x reference)
#include <cuda_runtime.h>
#include <math.h>

#define NB 8
#define NG 32768
#define NA 64
#define ND 128
#define GT 64
#define NTILES (NB*(NG/GT))   // 4096

// ---- scratch (static device allocations are allowed) ----
__device__ float g_gto[NB*NG*NA];        // 64 MB
__device__ float g_mo [NB*NG*ND];        // 128 MB
__device__ float g_gnorm2 [NB*NA];
__device__ float g_monorm2[NB*ND];
__device__ float g_ceff[NB*NA*ND];
__device__ float g_invmo[NB*ND];
__device__ float g_u[ND];
__device__ float g_t[ND];
__device__ float g_W1t[ND*ND];           // layer-1 weights, [d][e]
__device__ float g_W2t[ND*ND];           // layer-2 weights, [d][e]

static __device__ __forceinline__ void fma4(float* acc, float v, float4 w) {
    acc[0] = fmaf(v, w.x, acc[0]);
    acc[1] = fmaf(v, w.y, acc[1]);
    acc[2] = fmaf(v, w.z, acc[2]);
    acc[3] = fmaf(v, w.w, acc[3]);
}

// ---------- init: zero accumulators, seed output with W_prop_b ----------
__global__ void initK(float* out, const float* __restrict__ wpb) {
    int i = blockIdx.x * blockDim.x + threadIdx.x;
    if (i < NB*NA) g_gnorm2[i] = 0.f;
    if (i < NB*ND) g_monorm2[i] = 0.f;
    if (i < NB)    out[i] = wpb[0];
}

// ---------- gto: basis values + sum_g gto^2 ----------
__global__ void __launch_bounds__(256) gtoK(const float* __restrict__ dist,
                                            const int* __restrict__ qn,
                                            const int* __restrict__ ao,
                                            const float* __restrict__ zeta) {
    int b  = blockIdx.y;
    int a  = threadIdx.x & 63;
    int gl = threadIdx.x >> 6;           // 0..3
    int q  = qn[b*NA + a];
    float z = zeta[ao[b*NA + a]];
    long base = ((long)b*NG + (long)blockIdx.x*512) * NA;
    float acc = 0.f;
    for (int i = gl; i < 512; i += 4) {
        float d  = dist[base + (long)i*NA + a];
        float zd = z * d;
        float p  = (q == 0) ? 1.0f : ((q == 1) ? d : d*d);
        float v  = p * __expf(-zd*zd);
        g_gto[base + (long)i*NA + a] = v;
        acc = fmaf(v, v, acc);
    }
    __shared__ float s[4][64];
    s[gl][a] = acc;
    __syncthreads();
    if (threadIdx.x < 64) {
        float t = s[0][a] + s[1][a] + s[2][a] + s[3][a];
        atomicAdd(&g_gnorm2[b*NA + a], t);
    }
}

// ---------- ceff = coef/||c||_a / ||gto||_g ----------
__global__ void prepK(const int* __restrict__ ao, const float* __restrict__ coef) {
    int b = blockIdx.x;
    int d = threadIdx.x;                  // 0..127
    __shared__ float rg[64];
    __shared__ int   aos[64];
    if (d < 64) {
        aos[d] = ao[b*NA + d];
        rg[d]  = 1.f / fmaxf(sqrtf(g_gnorm2[b*NA + d]), 1e-12f);
    }
    __syncthreads();
    float cn = 0.f;
    for (int a = 0; a < NA; a++) { float c = coef[aos[a]*ND + d]; cn = fmaf(c, c, cn); }
    float rc = 1.f / fmaxf(sqrtf(cn), 1e-12f);
    for (int a = 0; a < NA; a++)
        g_ceff[(b*NA + a)*ND + d] = coef[aos[a]*ND + d] * rc * rg[a];
}

// ---------- fold layer 0 into (u, t) ----------
__global__ void utK(const float* __restrict__ wprew, const float* __restrict__ wpreb,
                    const float* __restrict__ wfw,   const float* __restrict__ wfb) {
    int e = threadIdx.x;
    float u = 0.f, t = 0.f;
    for (int d = 0; d < ND; d++) {
        float w = wfw[e*ND + d];          // layer 0, [e][d]
        u = fmaf(w, wprew[d], u);
        t = fmaf(w, wpreb[d], t);
    }
    g_u[e] = u;
    g_t[e] = t + wfb[e];
}

// ---------- transpose W1, W2 to [d][e] ----------
__global__ void transWK(const float* __restrict__ wfw) {
    float* dst = (blockIdx.x == 0) ? g_W1t : g_W2t;
    const float* src = wfw + (blockIdx.x + 1) * ND * ND;   // layers 1, 2
    for (int i = threadIdx.x; i < ND*ND; i += blockDim.x) {
        int e = i >> 7, d = i & 127;
        dst[d*ND + e] = src[i];
    }
}

// ---------- mo GEMM + column sums of squares ----------
__global__ void __launch_bounds__(256) moK() {
    extern __shared__ float sm[];
    float* gtoS   = sm;                   // 64*64
    float* ceffS  = sm + 64*64;           // 64*128
    float* colsum = ceffS + 64*128;       // 128
    int b  = blockIdx.y;
    int g0 = blockIdx.x * 64;
    int tid = threadIdx.x;
    if (tid < 128) colsum[tid] = 0.f;

    const float* cef = g_ceff + b*NA*ND;
    for (int i = tid; i < 64*128/4; i += 256)
        ((float4*)ceffS)[i] = ((const float4*)cef)[i];
    long gb = ((long)b*NG + g0) * NA;
    for (int i = tid; i < 64*64/4; i += 256)
        ((float4*)gtoS)[i] = ((const float4*)(g_gto + gb))[i];
    __syncthreads();

    int eq = tid & 31, gq = tid >> 5;
    float acc[8][4];
    #pragma unroll
    for (int r = 0; r < 8; r++) { acc[r][0]=0.f; acc[r][1]=0.f; acc[r][2]=0.f; acc[r][3]=0.f; }

    #pragma unroll 4
    for (int a4 = 0; a4 < 16; a4++) {
        float4 w[4];
        #pragma unroll
        for (int k = 0; k < 4; k++) w[k] = *(const float4*)&ceffS[(4*a4 + k)*ND + 4*eq];
        #pragma unroll
        for (int r = 0; r < 8; r++) {
            float4 v = *(const float4*)&gtoS[(gq*8 + r)*64 + 4*a4];
            fma4(acc[r], v.x, w[0]); fma4(acc[r], v.y, w[1]);
            fma4(acc[r], v.z, w[2]); fma4(acc[r], v.w, w[3]);
        }
    }

    float cs[4] = {0.f, 0.f, 0.f, 0.f};
    long mb = ((long)b*NG + g0) * ND;
    #pragma unroll
    for (int r = 0; r < 8; r++) {
        float4 o = make_float4(acc[r][0], acc[r][1], acc[r][2], acc[r][3]);
        *(float4*)&g_mo[mb + (gq*8 + r)*ND + 4*eq] = o;
        #pragma unroll
        for (int j = 0; j < 4; j++) cs[j] = fmaf(acc[r][j], acc[r][j], cs[j]);
    }
    __syncthreads();     // colsum zeroed + all reads of gtoS done
    #pragma unroll
    for (int j = 0; j < 4; j++) atomicAdd(&colsum[4*eq + j], cs[j]);
    __syncthreads();
    if (tid < 128) atomicAdd(&g_monorm2[b*ND + tid], colsum[tid]);
}

// ---------- invmo = sqrt(Ne/128)/max(||mo||,eps) ----------
__global__ void invmoK(const float* __restrict__ Ne) {
    int i = blockIdx.x * blockDim.x + threadIdx.x;
    if (i < NB*ND) {
        int b = i >> 7;
        float s = sqrtf(Ne[b] / (float)ND);
        g_invmo[i] = s / fmaxf(sqrtf(g_monorm2[i]), 1e-12f);
    }
}

// ---------- persistent fused MLP: density -> v1 -> GEMM1 -> GEMM2 -> reduce ----------
#define BSTRIDE 132
__global__ void __launch_bounds__(256) mlpK(const float* __restrict__ wfb,
                                            const float* __restrict__ wpw,
                                            float* __restrict__ out) {
    extern __shared__ float sm[];
    float* W1   = sm;                     // 128*128 [d][e]
    float* W2   = W1 + ND*ND;             // 128*128 [d][e]
    float* bufA = W2 + ND*ND;             // 64*128
    float* bufB = bufA + GT*ND;           // 64*132 (padded)
    float* us   = bufB + GT*BSTRIDE;
    float* ts   = us  + ND;
    float* b1s  = ts  + ND;
    float* b2s  = b1s + ND;
    float* wps  = b2s + ND;
    float* inv  = wps + ND;
    float* dens = inv + ND;               // 64
    float* red  = dens + GT;              // 8
    int tid = threadIdx.x;

    for (int i = tid; i < ND*ND; i += 256) { W1[i] = g_W1t[i]; W2[i] = g_W2t[i]; }
    if (tid < ND) {
        us[tid]  = g_u[tid];
        ts[tid]  = g_t[tid];
        b1s[tid] = wfb[ND + tid];         // layer-1 bias
        b2s[tid] = wfb[2*ND + tid];       // layer-2 bias
        wps[tid] = wpw[tid];
    }
    int eq = tid & 31, gq = tid >> 5;

    for (int tile = blockIdx.x; tile < NTILES; tile += gridDim.x) {
        int b  = tile >> 9;               // 512 tiles per molecule
        int g0 = (tile & 511) * GT;
        __syncthreads();                  // buffers free from previous tile
        if (tid < ND) inv[tid] = g_invmo[b*ND + tid];

        long mbase = ((long)b*NG + g0) * ND;
        for (int i = tid; i < GT*32; i += 256) {
            int g = i >> 5, c = i & 31;
            *(float4*)&bufB[g*BSTRIDE + 4*c] = *(const float4*)&g_mo[mbase + (long)g*ND + 4*c];
        }
        __syncthreads();

        // density per grid point (4 threads/g, d interleaved -> conflict-free)
        {
            int g = tid >> 2, l4 = tid & 3;
            float s = 0.f;
            #pragma unroll
            for (int k = 0; k < 32; k++) {
                int d = l4 + 4*k;
                float m = bufB[g*BSTRIDE + d] * inv[d];
                s = fmaf(m, m, s);
            }
            s += __shfl_xor_sync(0xffffffffu, s, 1);
            s += __shfl_xor_sync(0xffffffffu, s, 2);
            if (l4 == 0) dens[g] = s;
        }
        __syncthreads();

        // v1 = relu(density*u + t)  (layer 0+1 folded)
        for (int i = tid; i < GT*ND; i += 256) {
            int g = i >> 7, e = i & 127;
            bufA[i] = fmaxf(fmaf(dens[g], us[e], ts[e]), 0.f);
        }
        __syncthreads();

        // GEMM1: bufB = relu(bufA @ W1^T + b1)
        float acc[8][4];
        {
            float4 bb = *(const float4*)&b1s[4*eq];
            #pragma unroll
            for (int r = 0; r < 8; r++) { acc[r][0]=bb.x; acc[r][1]=bb.y; acc[r][2]=bb.z; acc[r][3]=bb.w; }
        }
        #pragma unroll 4
        for (int d4 = 0; d4 < 32; d4++) {
            float4 w[4];
            #pragma unroll
            for (int k = 0; k < 4; k++) w[k] = *(const float4*)&W1[(4*d4 + k)*ND + 4*eq];
            #pragma unroll
            for (int r = 0; r < 8; r++) {
                float4 v = *(const float4*)&bufA[(gq*8 + r)*ND + 4*d4];
                fma4(acc[r], v.x, w[0]); fma4(acc[r], v.y, w[1]);
                fma4(acc[r], v.z, w[2]); fma4(acc[r], v.w, w[3]);
            }
        }
        #pragma unroll
        for (int r = 0; r < 8; r++) {
            float4 o = make_float4(fmaxf(acc[r][0],0.f), fmaxf(acc[r][1],0.f),
                                   fmaxf(acc[r][2],0.f), fmaxf(acc[r][3],0.f));
            *(float4*)&bufB[(gq*8 + r)*BSTRIDE + 4*eq] = o;
        }
        __syncthreads();

        // GEMM2 + fused epilogue: relu, dot with W_prop, block reduce
        {
            float4 bb = *(const float4*)&b2s[4*eq];
            #pragma unroll
            for (int r = 0; r < 8; r++) { acc[r][0]=bb.x; acc[r][1]=bb.y; acc[r][2]=bb.z; acc[r][3]=bb.w; }
        }
        #pragma unroll 4
        for (int d4 = 0; d4 < 32; d4++) {
            float4 w[4];
            #pragma unroll
            for (int k = 0; k < 4; k++) w[k] = *(const float4*)&W2[(4*d4 + k)*ND + 4*eq];
            #pragma unroll
            for (int r = 0; r < 8; r++) {
                float4 v = *(const float4*)&bufB[(gq*8 + r)*BSTRIDE + 4*d4];
                fma4(acc[r], v.x, w[0]); fma4(acc[r], v.y, w[1]);
                fma4(acc[r], v.z, w[2]); fma4(acc[r], v.w, w[3]);
            }
        }
        float local = 0.f;
        {
            float4 wp4 = *(const float4*)&wps[4*eq];
            #pragma unroll
            for (int r = 0; r < 8; r++) {
                local += fmaxf(acc[r][0],0.f)*wp4.x + fmaxf(acc[r][1],0.f)*wp4.y
                       + fmaxf(acc[r][2],0.f)*wp4.z + fmaxf(acc[r][3],0.f)*wp4.w;
            }
        }
        #pragma unroll
        for (int off = 16; off; off >>= 1) local += __shfl_xor_sync(0xffffffffu, local, off);
        if (eq == 0) red[gq] = local;
        __syncthreads();
        if (tid == 0) {
            float s = 0.f;
            #pragma unroll
            for (int w = 0; w < 8; w++) s += red[w];
            atomicAdd(&out[b], s);
        }
    }
}

extern "C" void kernel_launch(void* const* d_in, const int* in_sizes, int n_in,
                              void* d_out, int out_size) {
    const float* dist  = (const float*)d_in[0];
    const int*   qn    = (const int*)  d_in[1];
    const int*   ao    = (const int*)  d_in[2];
    const float* Ne    = (const float*)d_in[3];
    const float* coef  = (const float*)d_in[4];
    const float* zeta  = (const float*)d_in[5];
    const float* wprew = (const float*)d_in[6];
    const float* wpreb = (const float*)d_in[7];
    const float* wfw   = (const float*)d_in[8];
    const float* wfb   = (const float*)d_in[9];
    const float* wpw   = (const float*)d_in[10];
    const float* wpb   = (const float*)d_in[11];
    float* out = (float*)d_out;

    const int moSmem  = (64*64 + 64*128 + 128) * 4;
    const int mlpSmem = (ND*ND*2 + GT*ND + GT*BSTRIDE + ND*6 + GT + 8) * 4;
    cudaFuncSetAttribute(moK,  cudaFuncAttributeMaxDynamicSharedMemorySize, moSmem);
    cudaFuncSetAttribute(mlpK, cudaFuncAttributeMaxDynamicSharedMemorySize, mlpSmem);

    int sms = 148;
    cudaDeviceGetAttribute(&sms, cudaDevAttrMultiProcessorCount, 0);

    initK<<<1, 1024>>>(out, wpb);
    gtoK<<<dim3(NG/512, NB), 256>>>(dist, qn, ao, zeta);
    prepK<<<NB, 128>>>(ao, coef);
    utK<<<1, 128>>>(wprew, wpreb, wfw, wfb);
    transWK<<<2, 256>>>(wfw);
    moK<<<dim3(NG/64, NB), 256, moSmem>>>();
    invmoK<<<1, 1024>>>(Ne);
    mlpK<<<sms, 256, mlpSmem>>>(wfb, wpw, out);
}